// round 2
// baseline (speedup 1.0000x reference)
#include <cuda_runtime.h>
#include <cstdint>

// Suffix (reverse cumulative) max along last dim.
// (8, 1, 2048, 2048) fp32 -> 16384 rows x 2048 cols.
// One CTA per row, 128 threads, 16 elems/thread via 4x float4 (LDG.128).
// Single __syncthreads; streaming cache hints (touch-once data).

#define ROW_LEN 2048
#define THREADS 128

__device__ __forceinline__ float neg_inf() {
    return __int_as_float(0xff800000);
}

__global__ void __launch_bounds__(THREADS)
suffix_max_kernel(const float* __restrict__ in, float* __restrict__ out) {
    const unsigned row_off = blockIdx.x * (unsigned)ROW_LEN;   // < 2^25, 32-bit safe
    const float4* __restrict__ rin  = reinterpret_cast<const float4*>(in  + row_off);
    float4* __restrict__       rout = reinterpret_cast<float4*>(out + row_off);

    const int t    = threadIdx.x;
    const int lane = t & 31;
    const int warp = t >> 5;
    const int vi   = t * 4;

    // ---- load 16 contiguous floats (4x LDG.128, streaming) ----
    float4 a = __ldcs(rin + vi + 0);
    float4 b = __ldcs(rin + vi + 1);
    float4 c = __ldcs(rin + vi + 2);
    float4 d = __ldcs(rin + vi + 3);

    // ---- suffix max within the 16-element chunk (right to left) ----
    d.z = fmaxf(d.z, d.w); d.y = fmaxf(d.y, d.z); d.x = fmaxf(d.x, d.y);
    c.w = fmaxf(c.w, d.x);
    c.z = fmaxf(c.z, c.w); c.y = fmaxf(c.y, c.z); c.x = fmaxf(c.x, c.y);
    b.w = fmaxf(b.w, c.x);
    b.z = fmaxf(b.z, b.w); b.y = fmaxf(b.y, b.z); b.x = fmaxf(b.x, b.y);
    a.w = fmaxf(a.w, b.x);
    a.z = fmaxf(a.z, a.w); a.y = fmaxf(a.y, a.z); a.x = fmaxf(a.x, a.y);
    const float chunk_max = a.x;

    // ---- warp-level inclusive suffix scan of chunk maxima ----
    float incl = chunk_max;
    #pragma unroll
    for (int off = 1; off < 32; off <<= 1) {
        float x = __shfl_down_sync(0xffffffffu, incl, off);
        if (lane + off < 32) incl = fmaxf(incl, x);
    }
    // exclusive carry from lanes strictly to the right within this warp
    float carry = __shfl_down_sync(0xffffffffu, incl, 1);
    if (lane == 31) carry = neg_inf();

    // ---- cross-warp carry: 4 warp maxima via smem, one barrier ----
    __shared__ float wmax[4];
    if (lane == 0) wmax[warp] = incl;   // incl at lane 0 == warp's max
    __syncthreads();

    if (warp < 3) carry = fmaxf(carry, wmax[3]);
    if (warp < 2) carry = fmaxf(carry, wmax[2]);
    if (warp < 1) carry = fmaxf(carry, wmax[1]);

    // ---- apply carry and store (streaming) ----
    a.x = fmaxf(a.x, carry); a.y = fmaxf(a.y, carry);
    a.z = fmaxf(a.z, carry); a.w = fmaxf(a.w, carry);
    b.x = fmaxf(b.x, carry); b.y = fmaxf(b.y, carry);
    b.z = fmaxf(b.z, carry); b.w = fmaxf(b.w, carry);
    c.x = fmaxf(c.x, carry); c.y = fmaxf(c.y, carry);
    c.z = fmaxf(c.z, carry); c.w = fmaxf(c.w, carry);
    d.x = fmaxf(d.x, carry); d.y = fmaxf(d.y, carry);
    d.z = fmaxf(d.z, carry); d.w = fmaxf(d.w, carry);

    __stcs(rout + vi + 0, a);
    __stcs(rout + vi + 1, b);
    __stcs(rout + vi + 2, c);
    __stcs(rout + vi + 3, d);
}

extern "C" void kernel_launch(void* const* d_in, const int* in_sizes, int n_in,
                              void* d_out, int out_size) {
    const float* x = (const float*)d_in[0];
    float* out = (float*)d_out;
    const int n_rows = out_size / ROW_LEN;   // 16384
    suffix_max_kernel<<<n_rows, THREADS>>>(x, out);
}